// round 1
// baseline (speedup 1.0000x reference)
#include <cuda_runtime.h>

#define N_NODES 100000
#define N_EDGES 1600000
#define HMW 32            // concatenated mu(16) | logstd(16)
#define OUTC 16

// ---------------- scratch (device globals; no allocations allowed) -------------
__device__ float g_deg [N_NODES];          // in-degree count (dst)
__device__ float g_dis [N_NODES];          // rsqrt(1 + deg)
__device__ float g_acc0[N_NODES * 2];      // layer-1 aggregation of dis*x
__device__ float g_gvec[N_NODES * HMW];    // g = dis * (h @ [Wmu|Wls])
__device__ float g_acc1[N_NODES * HMW];    // layer-2 aggregation of g[src]
__device__ int   g_is64;                   // edge_index dtype flag

// ---------------- dtype detection: int64 values <100k have zero high words ------
__global__ void k_detect(const unsigned* ei_words) {
    __shared__ unsigned s_or[256];
    unsigned v = 0;
    for (int i = threadIdx.x; i < 4096; i += 256)
        v |= ei_words[2 * i + 1];
    s_or[threadIdx.x] = v;
    __syncthreads();
    for (int s = 128; s > 0; s >>= 1) {
        if (threadIdx.x < s) s_or[threadIdx.x] |= s_or[threadIdx.x + s];
        __syncthreads();
    }
    if (threadIdx.x == 0) g_is64 = (s_or[0] == 0u) ? 1 : 0;
}

__device__ __forceinline__ void load_edge(const void* ei, int e, int& src, int& dst) {
    if (g_is64) {
        const long long* p = (const long long*)ei;
        src = (int)p[e];
        dst = (int)p[N_EDGES + e];
    } else {
        const int* p = (const int*)ei;
        src = p[e];
        dst = p[N_EDGES + e];
    }
}

// ---------------- zero accumulators (must happen every replay) ------------------
__global__ void k_zero() {
    int i = blockIdx.x * 256 + threadIdx.x;
    if (i < N_NODES * HMW) g_acc1[i] = 0.0f;
    if (i < N_NODES * 2)   g_acc0[i] = 0.0f;
    if (i < N_NODES)       g_deg[i]  = 0.0f;
}

// ---------------- degree (count of dst occurrences) -----------------------------
__global__ void k_deg(const void* ei) {
    int e = blockIdx.x * 256 + threadIdx.x;
    if (e >= N_EDGES) return;
    int dst;
    if (g_is64) dst = (int)((const long long*)ei)[N_EDGES + e];
    else        dst = ((const int*)ei)[N_EDGES + e];
    atomicAdd(&g_deg[dst], 1.0f);
}

__global__ void k_dis() {
    int n = blockIdx.x * 256 + threadIdx.x;
    if (n < N_NODES) g_dis[n] = rsqrtf(1.0f + g_deg[n]);
}

// ---------------- layer-1 scatter: acc0[dst] += dis[src] * x[src]  (2 feats) ----
__global__ void k_scatter0(const void* ei, const float* x) {
    int e = blockIdx.x * 256 + threadIdx.x;
    if (e >= N_EDGES) return;
    int src, dst;
    load_edge(ei, e, src, dst);
    float ds = g_dis[src];
    float2 xv = ((const float2*)x)[src];
    atomicAdd(&g_acc0[2 * dst + 0], ds * xv.x);
    atomicAdd(&g_acc0[2 * dst + 1], ds * xv.y);
}

// ---------------- dense: h = relu(aggX @ W1 + b1); g = dis * (h @ [Wmu|Wls]) ----
// one warp per node; 8 nodes per 256-thread block
__global__ void k_hidden(const float* x, const float* W1, const float* b1,
                         const float* Wmu, const float* Wls) {
    __shared__ float sW[64][HMW];   // concatenated projection, 8KB
    __shared__ float sW1[2][64];
    __shared__ float sb1[64];
    __shared__ float sh[8][64];

    int t = threadIdx.x;
    for (int i = t; i < 64 * HMW; i += 256) {
        int k = i >> 5, j = i & 31;
        sW[k][j] = (j < OUTC) ? Wmu[k * OUTC + j] : Wls[k * OUTC + (j - OUTC)];
    }
    if (t < 128) sW1[t >> 6][t & 63] = W1[t];
    if (t < 64)  sb1[t] = b1[t];
    __syncthreads();

    int w = t >> 5, lane = t & 31;
    int n = blockIdx.x * 8 + w;
    if (n < N_NODES) {
        float d  = g_dis[n];
        float d2 = d * d;
        float a0 = d * g_acc0[2 * n + 0] + d2 * x[2 * n + 0];
        float a1 = d * g_acc0[2 * n + 1] + d2 * x[2 * n + 1];
        float h0 = fmaxf(0.0f, a0 * sW1[0][lane]      + a1 * sW1[1][lane]      + sb1[lane]);
        float h1 = fmaxf(0.0f, a0 * sW1[0][lane + 32] + a1 * sW1[1][lane + 32] + sb1[lane + 32]);
        sh[w][lane]      = h0;
        sh[w][lane + 32] = h1;
        __syncwarp();
        float s = 0.0f;
        #pragma unroll
        for (int k = 0; k < 64; k++)
            s += sh[w][k] * sW[k][lane];   // sh broadcast, sW conflict-free
        g_gvec[n * HMW + lane] = d * s;
    }
}

// ---------------- layer-2 scatter: acc1[dst][j] += g[src][j]  (32 feats) --------
// one thread per (edge, feature); warp shares one edge -> broadcast index loads,
// coalesced 128B gather of g[src] and coalesced atomics on acc1[dst]
__global__ void k_scatter1(const void* ei) {
    long long tid = (long long)blockIdx.x * 256 + threadIdx.x;
    if (tid >= (long long)N_EDGES * HMW) return;
    int e = (int)(tid >> 5), j = (int)(tid & 31);
    int src, dst;
    load_edge(ei, e, src, dst);
    atomicAdd(&g_acc1[dst * HMW + j], g_gvec[src * HMW + j]);
}

// ---------------- epilogue: out = dis*(acc1 + g) + bias; split mu / logstd ------
__global__ void k_out(const float* bmu, const float* bls, float* out) {
    int tid = blockIdx.x * 256 + threadIdx.x;
    if (tid >= N_NODES * HMW) return;
    int n = tid >> 5, j = tid & 31;
    float v = g_dis[n] * (g_acc1[tid] + g_gvec[tid]);
    if (j < OUTC) out[n * OUTC + j] = v + bmu[j];
    else          out[N_NODES * OUTC + n * OUTC + (j - OUTC)] = v + bls[j - OUTC];
}

extern "C" void kernel_launch(void* const* d_in, const int* in_sizes, int n_in,
                              void* d_out, int out_size) {
    const float* x    = (const float*)d_in[0];
    const void*  ei   = d_in[1];                 // int32 or int64, detected on device
    const float* W1   = (const float*)d_in[2];
    const float* b1   = (const float*)d_in[3];
    const float* Wmu  = (const float*)d_in[4];
    const float* bmu  = (const float*)d_in[5];
    const float* Wls  = (const float*)d_in[6];
    const float* bls  = (const float*)d_in[7];
    float* out = (float*)d_out;

    const int ZB  = (N_NODES * HMW + 255) / 256;          // 12500
    const int EB  = (N_EDGES + 255) / 256;                // 6250
    const int NB  = (N_NODES + 255) / 256;                // 391
    const int HB  = (N_NODES + 7) / 8;                    // 12500
    const long long s1t = (long long)N_EDGES * HMW;
    const int S1B = (int)((s1t + 255) / 256);             // 200000

    k_detect<<<1, 256>>>((const unsigned*)ei);
    k_zero<<<ZB, 256>>>();
    k_deg<<<EB, 256>>>(ei);
    k_dis<<<NB, 256>>>();
    k_scatter0<<<EB, 256>>>(ei, x);
    k_hidden<<<HB, 256>>>(x, W1, b1, Wmu, Wls);
    k_scatter1<<<S1B, 256>>>(ei);
    k_out<<<ZB, 256>>>(bmu, bls, out);
}

// round 2
// speedup vs baseline: 1.5586x; 1.5586x over previous
#include <cuda_runtime.h>

#define N_NODES 100000
#define N_EDGES 1600000
#define HMW 32            // concatenated mu(16) | logstd(16)
#define OUTC 16

// ---------------- scratch (device globals; no allocations allowed) -------------
__device__ float g_deg [N_NODES];          // in-degree count (dst)
__device__ float g_dis [N_NODES];          // rsqrt(1 + deg)
__device__ float g_acc0[N_NODES * 2];      // layer-1 aggregation of dis*x
__device__ float g_gvec[N_NODES * HMW];    // g = dis * (h @ [Wmu|Wls])
__device__ float g_acc1[N_NODES * HMW];    // layer-2 aggregation of g[src]
__device__ int   g_is64;                   // edge_index dtype flag

// ---------------- vectorized L2 reductions (sm_90+) -----------------------------
__device__ __forceinline__ void red_add_v4(float* addr, float4 v) {
    asm volatile("red.global.add.v4.f32 [%0], {%1, %2, %3, %4};"
                 :: "l"(addr), "f"(v.x), "f"(v.y), "f"(v.z), "f"(v.w) : "memory");
}
__device__ __forceinline__ void red_add_v2(float* addr, float a, float b) {
    asm volatile("red.global.add.v2.f32 [%0], {%1, %2};"
                 :: "l"(addr), "f"(a), "f"(b) : "memory");
}

// ---------------- dtype detection: int64 values <100k have zero high words ------
__global__ void k_detect(const unsigned* ei_words) {
    __shared__ unsigned s_or[256];
    unsigned v = 0;
    for (int i = threadIdx.x; i < 4096; i += 256)
        v |= ei_words[2 * i + 1];
    s_or[threadIdx.x] = v;
    __syncthreads();
    for (int s = 128; s > 0; s >>= 1) {
        if (threadIdx.x < s) s_or[threadIdx.x] |= s_or[threadIdx.x + s];
        __syncthreads();
    }
    if (threadIdx.x == 0) g_is64 = (s_or[0] == 0u) ? 1 : 0;
}

__device__ __forceinline__ void load_edge(const void* ei, int e, int& src, int& dst) {
    if (g_is64) {
        const long long* p = (const long long*)ei;
        src = (int)p[e];
        dst = (int)p[N_EDGES + e];
    } else {
        const int* p = (const int*)ei;
        src = p[e];
        dst = p[N_EDGES + e];
    }
}

// ---------------- zero accumulators (must happen every replay) ------------------
// total floats: acc1 3.2M + acc0 0.2M + deg 0.1M = 3.5M -> float4 stores
__global__ void k_zero() {
    int i = blockIdx.x * 256 + threadIdx.x;
    if (i < N_NODES * HMW / 4) ((float4*)g_acc1)[i] = make_float4(0.f, 0.f, 0.f, 0.f);
    if (i < N_NODES * 2 / 4)   ((float4*)g_acc0)[i] = make_float4(0.f, 0.f, 0.f, 0.f);
    if (i < N_NODES / 4)       ((float4*)g_deg )[i] = make_float4(0.f, 0.f, 0.f, 0.f);
}

// ---------------- degree (count of dst occurrences) -----------------------------
__global__ void k_deg(const void* ei) {
    int e = blockIdx.x * 256 + threadIdx.x;
    if (e >= N_EDGES) return;
    int dst;
    if (g_is64) dst = (int)((const long long*)ei)[N_EDGES + e];
    else        dst = ((const int*)ei)[N_EDGES + e];
    atomicAdd(&g_deg[dst], 1.0f);
}

__global__ void k_dis() {
    int n = blockIdx.x * 256 + threadIdx.x;
    if (n < N_NODES) g_dis[n] = rsqrtf(1.0f + g_deg[n]);
}

// ---------------- layer-1 scatter: acc0[dst] += dis[src] * x[src]  (2 feats) ----
__global__ void k_scatter0(const void* ei, const float* __restrict__ x) {
    int e = blockIdx.x * 256 + threadIdx.x;
    if (e >= N_EDGES) return;
    int src, dst;
    load_edge(ei, e, src, dst);
    float ds = g_dis[src];
    float2 xv = ((const float2*)x)[src];
    red_add_v2(&g_acc0[2 * dst], ds * xv.x, ds * xv.y);
}

// ---------------- dense: h = relu(aggX @ W1 + b1); g = dis * (h @ [Wmu|Wls]) ----
// one warp per node; 8 nodes per 256-thread block
__global__ void k_hidden(const float* __restrict__ x, const float* __restrict__ W1,
                         const float* __restrict__ b1,
                         const float* __restrict__ Wmu, const float* __restrict__ Wls) {
    __shared__ float sW[64][HMW];   // concatenated projection, 8KB
    __shared__ float sW1[2][64];
    __shared__ float sb1[64];
    __shared__ float sh[8][64];

    int t = threadIdx.x;
    for (int i = t; i < 64 * HMW; i += 256) {
        int k = i >> 5, j = i & 31;
        sW[k][j] = (j < OUTC) ? Wmu[k * OUTC + j] : Wls[k * OUTC + (j - OUTC)];
    }
    if (t < 128) sW1[t >> 6][t & 63] = W1[t];
    if (t < 64)  sb1[t] = b1[t];
    __syncthreads();

    int w = t >> 5, lane = t & 31;
    int n = blockIdx.x * 8 + w;
    if (n < N_NODES) {
        float d  = g_dis[n];
        float d2 = d * d;
        float a0 = d * g_acc0[2 * n + 0] + d2 * x[2 * n + 0];
        float a1 = d * g_acc0[2 * n + 1] + d2 * x[2 * n + 1];
        float h0 = fmaxf(0.0f, a0 * sW1[0][lane]      + a1 * sW1[1][lane]      + sb1[lane]);
        float h1 = fmaxf(0.0f, a0 * sW1[0][lane + 32] + a1 * sW1[1][lane + 32] + sb1[lane + 32]);
        sh[w][lane]      = h0;
        sh[w][lane + 32] = h1;
        __syncwarp();
        float s = 0.0f;
        #pragma unroll
        for (int k = 0; k < 64; k++)
            s += sh[w][k] * sW[k][lane];   // sh broadcast, sW conflict-free
        g_gvec[n * HMW + lane] = d * s;
    }
}

// ---------------- layer-2 scatter: acc1[dst][:] += g[src][:]  (32 feats) --------
// 8 threads per edge; each does one float4 gather + one red.v4 (128B coalesced)
__global__ void k_scatter1(const void* ei) {
    long long tid = (long long)blockIdx.x * 256 + threadIdx.x;
    if (tid >= (long long)N_EDGES * 8) return;
    int e = (int)(tid >> 3), q = (int)(tid & 7);
    int src, dst;
    load_edge(ei, e, src, dst);
    float4 v = ((const float4*)g_gvec)[src * 8 + q];
    red_add_v4(&g_acc1[dst * HMW + q * 4], v);
}

// ---------------- epilogue: out = dis*(acc1 + g) + bias; split mu / logstd ------
__global__ void k_out(const float* __restrict__ bmu, const float* __restrict__ bls,
                      float* __restrict__ out) {
    int tid = blockIdx.x * 256 + threadIdx.x;
    if (tid >= N_NODES * HMW) return;
    int n = tid >> 5, j = tid & 31;
    float v = g_dis[n] * (g_acc1[tid] + g_gvec[tid]);
    if (j < OUTC) out[n * OUTC + j] = v + bmu[j];
    else          out[N_NODES * OUTC + n * OUTC + (j - OUTC)] = v + bls[j - OUTC];
}

extern "C" void kernel_launch(void* const* d_in, const int* in_sizes, int n_in,
                              void* d_out, int out_size) {
    const float* x    = (const float*)d_in[0];
    const void*  ei   = d_in[1];                 // int32 or int64, detected on device
    const float* W1   = (const float*)d_in[2];
    const float* b1   = (const float*)d_in[3];
    const float* Wmu  = (const float*)d_in[4];
    const float* bmu  = (const float*)d_in[5];
    const float* Wls  = (const float*)d_in[6];
    const float* bls  = (const float*)d_in[7];
    float* out = (float*)d_out;

    const int ZB  = (N_NODES * HMW / 4 + 255) / 256;      // 3125 (covers all zero ranges)
    const int EB  = (N_EDGES + 255) / 256;                // 6250
    const int NB  = (N_NODES + 255) / 256;                // 391
    const int HB  = (N_NODES + 7) / 8;                    // 12500
    const int OB  = (N_NODES * HMW + 255) / 256;          // 12500
    const int S1B = (int)(((long long)N_EDGES * 8 + 255) / 256);  // 50000

    k_detect<<<1, 256>>>((const unsigned*)ei);
    k_zero<<<ZB, 256>>>();
    k_deg<<<EB, 256>>>(ei);
    k_dis<<<NB, 256>>>();
    k_scatter0<<<EB, 256>>>(ei, x);
    k_hidden<<<HB, 256>>>(x, W1, b1, Wmu, Wls);
    k_scatter1<<<S1B, 256>>>(ei);
    k_out<<<OB, 256>>>(bmu, bls, out);
}